// round 10
// baseline (speedup 1.0000x reference)
#include <cuda_runtime.h>
#include <cstdint>
#include <cstddef>

#define T_STEPS 2048
#define B_SZ    128
#define H_SZ    200
#define IN_SZ   88
#define OUT_SZ  88
#define G4H     800
#define CL_N    4        // CTAs per cluster
#define BG_SZ   4        // batches per cluster
#define U_PER   50       // hidden units per CTA

// ---------------- scratch (static device globals) ---------------------------
__device__ float g_gx[(size_t)T_STEPS * G4H * B_SZ];   // [T][4H][B]
__device__ float g_y [(size_t)T_STEPS * B_SZ * H_SZ];  // [T][B][H]

__device__ __forceinline__ float sigm(float x) {
    return __frcp_rn(1.0f + __expf(-x));
}
__device__ __forceinline__ float tanh_f(float x) {
    float e = __expf(-2.0f * fabsf(x));
    float r = (1.0f - e) * __frcp_rn(1.0f + e);
    return copysignf(r, x);
}
__device__ __forceinline__ float2 unpack2(unsigned long long v) {
    float2 r;
    asm("mov.b64 {%0, %1}, %2;" : "=f"(r.x), "=f"(r.y) : "l"(v));
    return r;
}
#define FMA2(acc, a, b) \
    asm("fma.rn.f32x2 %0, %1, %2, %0;" : "+l"(acc) : "l"(a), "l"(b))

// ---------------- projection GEMM (unchanged — known good) -------------------
__global__ void proj_kernel(const float* __restrict__ A, const float* __restrict__ W,
                            const float* __restrict__ b1, const float* __restrict__ b2,
                            float* __restrict__ out, int K, int R, int mode)
{
    __shared__ float w_sm[16 * H_SZ];   // max K = 200

    int t   = blockIdx.y;
    int r0  = blockIdx.x * 16;
    int tid = threadIdx.x;
    int K4  = K >> 2;

    for (int i = tid; i < 16 * K4; i += 128) {
        int r = i / K4, kk = i % K4, rg = r0 + r;
        float4 v = make_float4(0.f, 0.f, 0.f, 0.f);
        if (rg < R) v = ((const float4*)(W + (size_t)rg * K))[kk];
        ((float4*)w_sm)[i] = v;
    }
    __syncthreads();

    int b = tid;
    unsigned long long acc[16];
#pragma unroll
    for (int r = 0; r < 16; r++) acc[r] = 0ULL;

    const ulonglong2* xrow = (const ulonglong2*)(A + ((size_t)t * B_SZ + b) * K);
#pragma unroll 2
    for (int kk = 0; kk < K4; kk++) {
        ulonglong2 xv = __ldg(xrow + kk);
#pragma unroll
        for (int r = 0; r < 16; r++) {
            ulonglong2 wv = *((const ulonglong2*)(w_sm + r * K) + kk);
            FMA2(acc[r], xv.x, wv.x);
            FMA2(acc[r], xv.y, wv.y);
        }
    }

    if (mode == 0) {
#pragma unroll
        for (int r = 0; r < 16; r++) {
            int rg = r0 + r;
            if (rg < R) {
                float2 p = unpack2(acc[r]);
                out[((size_t)t * R + rg) * B_SZ + b] =
                    p.x + p.y + b1[rg] + b2[rg];
            }
        }
    } else {
#pragma unroll
        for (int r = 0; r < 16; r++) {
            int rg = r0 + r;
            if (rg < R) {
                float2 p = unpack2(acc[r]);
                out[((size_t)t * B_SZ + b) * R + rg] = sigm(p.x + p.y + b1[rg]);
            }
        }
    }
}

// ---------------- persistent LSTM: 4-CTA cluster, (u,ks) thread mapping ------
// Grid (4, 32), cluster (4,1,1). CTA rank jg owns 50 hidden units.
// Thread (tid<200): u = tid>>2 (unit), ks = tid&3 (k-quarter, 50 k each).
// Each thread computes partials for ALL 4 batches over its k-slice (weights
// unique per lane — no duplicated smem requests); i/f gate weights live in
// registers; shfl_xor(1,2) over the 4 ks-lanes completes the sums; the thread
// then owns batch b=ks for activations/state/stores.
#define W_WORDS  (4 * U_PER * H_SZ)             // 40000
#define HS_OFF   W_WORDS
#define HS_BUF   (BG_SZ * 204)                  // 816
#define NTHR     256
__global__ void __cluster_dims__(CL_N, 1, 1)
lstm_kernel(const float* __restrict__ gx,   // [T][4H][B]
            const float* __restrict__ whh,  // [4H][H]
            float* __restrict__ y,          // [T][B][H]
            float* __restrict__ hn, float* __restrict__ cn)
{
    extern __shared__ float sm[];
    float* w_sm = sm;                       // 40000 floats [g][u][k]

    int tid = threadIdx.x;
    int jg  = blockIdx.x;                   // cluster rank
    int bg  = blockIdx.y;                   // batch-group 0..31

    // stage this CTA's weight slice (coalesced over k)
    for (int i = tid; i < W_WORDS; i += NTHR) {
        int g = i / (U_PER * H_SZ), rem = i % (U_PER * H_SZ);
        int u = rem / H_SZ, k = rem % H_SZ;
        w_sm[i] = whh[(size_t)(g * H_SZ + jg * U_PER + u) * H_SZ + k];
    }
    // zero h double-buffer
    for (int i = tid; i < 2 * HS_BUF; i += NTHR) sm[HS_OFF + i] = 0.f;
    __syncthreads();
    asm volatile("barrier.cluster.arrive.aligned;" ::: "memory");
    asm volatile("barrier.cluster.wait.aligned;"   ::: "memory");

    unsigned smem_u32;
    {
        unsigned long long tmp;
        asm("cvta.to.shared.u64 %0, %1;" : "=l"(tmp) : "l"(sm));
        smem_u32 = (unsigned)tmp;
    }

    bool active = tid < 200;
    int atid = active ? tid : 0;
    int u  = atid >> 2;                     // 0..49
    int ks = atid & 3;                      // k-quarter; also owned batch
    int j = jg * U_PER + u;
    int bglob = bg * BG_SZ + ks;
    float c = 0.f;

    // i/f gate weight slices -> registers (held for all 2048 steps)
    unsigned long long wi_r[25], wf_r[25];
    {
        const unsigned long long* pi =
            (const unsigned long long*)(w_sm + 0 * U_PER * H_SZ + u * H_SZ + ks * 50);
        const unsigned long long* pf =
            (const unsigned long long*)(w_sm + 1 * U_PER * H_SZ + u * H_SZ + ks * 50);
#pragma unroll
        for (int kk = 0; kk < 25; kk++) { wi_r[kk] = pi[kk]; wf_r[kk] = pf[kk]; }
    }
    const unsigned long long* wg2 =
        (const unsigned long long*)(w_sm + 2 * U_PER * H_SZ + u * H_SZ + ks * 50);
    const unsigned long long* wo2 =
        (const unsigned long long*)(w_sm + 3 * U_PER * H_SZ + u * H_SZ + ks * 50);

    // remote h slots: this thread publishes h(b=ks, j) to all 4 ranks
    unsigned rh[CL_N];
    {
        unsigned hloc = smem_u32 + (HS_OFF + ks * 204 + j) * 4u;
#pragma unroll
        for (int r = 0; r < CL_N; r++)
            asm("mapa.shared::cluster.u32 %0, %1, %2;"
                : "=r"(rh[r]) : "r"(hloc), "r"(r));
    }

    // preload gx for t = 0 (batch b=ks)
    float gi = 0.f, gf = 0.f, gg = 0.f, go = 0.f;
    if (active) {
        size_t base = (size_t)j * B_SZ + bglob;
        gi = gx[base];
        gf = gx[base + 200 * B_SZ];
        gg = gx[base + 400 * B_SZ];
        go = gx[base + 600 * B_SZ];
    }

    for (int t = 0; t < T_STEPS; t++) {
        const float* hb = sm + HS_OFF + (t & 1) * HS_BUF + ks * 50;
        const unsigned long long* h0 = (const unsigned long long*)(hb + 0 * 204);
        const unsigned long long* h1 = (const unsigned long long*)(hb + 1 * 204);
        const unsigned long long* h2 = (const unsigned long long*)(hb + 2 * 204);
        const unsigned long long* h3 = (const unsigned long long*)(hb + 3 * 204);

        unsigned long long ai[4], af[4], ag[4], ao[4];
#pragma unroll
        for (int b = 0; b < 4; b++) { ai[b] = 0ULL; af[b] = 0ULL; ag[b] = 0ULL; ao[b] = 0ULL; }

#pragma unroll
        for (int kk = 0; kk < 25; kk++) {
            unsigned long long hv0 = h0[kk], hv1 = h1[kk], hv2 = h2[kk], hv3 = h3[kk];
            unsigned long long wg = wg2[kk], wo = wo2[kk];
            unsigned long long wi = wi_r[kk], wf = wf_r[kk];
            FMA2(ai[0], hv0, wi); FMA2(ai[1], hv1, wi);
            FMA2(ai[2], hv2, wi); FMA2(ai[3], hv3, wi);
            FMA2(af[0], hv0, wf); FMA2(af[1], hv1, wf);
            FMA2(af[2], hv2, wf); FMA2(af[3], hv3, wf);
            FMA2(ag[0], hv0, wg); FMA2(ag[1], hv1, wg);
            FMA2(ag[2], hv2, wg); FMA2(ag[3], hv3, wg);
            FMA2(ao[0], hv0, wo); FMA2(ao[1], hv1, wo);
            FMA2(ao[2], hv2, wo); FMA2(ao[3], hv3, wo);
        }

        // collapse f32x2 pairs, then butterfly over the 4 ks-lanes
        float si[4], sf[4], sg[4], so[4];
#pragma unroll
        for (int b = 0; b < 4; b++) {
            float2 p;
            p = unpack2(ai[b]); si[b] = p.x + p.y;
            p = unpack2(af[b]); sf[b] = p.x + p.y;
            p = unpack2(ag[b]); sg[b] = p.x + p.y;
            p = unpack2(ao[b]); so[b] = p.x + p.y;
        }
#pragma unroll
        for (int b = 0; b < 4; b++) {
            si[b] += __shfl_xor_sync(0xFFFFFFFFu, si[b], 1);
            si[b] += __shfl_xor_sync(0xFFFFFFFFu, si[b], 2);
            sf[b] += __shfl_xor_sync(0xFFFFFFFFu, sf[b], 1);
            sf[b] += __shfl_xor_sync(0xFFFFFFFFu, sf[b], 2);
            sg[b] += __shfl_xor_sync(0xFFFFFFFFu, sg[b], 1);
            sg[b] += __shfl_xor_sync(0xFFFFFFFFu, sg[b], 2);
            so[b] += __shfl_xor_sync(0xFFFFFFFFu, so[b], 1);
            so[b] += __shfl_xor_sync(0xFFFFFFFFu, so[b], 2);
        }
        // this thread owns batch b = ks
        float vi = (ks == 0) ? si[0] : (ks == 1) ? si[1] : (ks == 2) ? si[2] : si[3];
        float vf = (ks == 0) ? sf[0] : (ks == 1) ? sf[1] : (ks == 2) ? sf[2] : sf[3];
        float vg = (ks == 0) ? sg[0] : (ks == 1) ? sg[1] : (ks == 2) ? sg[2] : sg[3];
        float vo = (ks == 0) ? so[0] : (ks == 1) ? so[1] : (ks == 2) ? so[2] : so[3];

        float I = sigm(vi + gi);
        float F = sigm(vf + gf);
        float G = tanh_f(vg + gg);
        float O = sigm(vo + go);
        c = F * c + I * G;
        float h = O * tanh_f(c);

        // push h into every cluster CTA's next-step buffer
        if (active) {
            unsigned bofs = (unsigned)(((t + 1) & 1) * (HS_BUF * 4));
#pragma unroll
            for (int r = 0; r < CL_N; r++) {
                asm volatile("st.shared::cluster.f32 [%0], %1;"
                             :: "r"(rh[r] + bofs), "f"(h) : "memory");
            }
        }

        // split barrier: overlap gmem output + next gx prefetch with peer skew
        asm volatile("barrier.cluster.arrive.aligned;" ::: "memory");

        float ni = 0.f, nf = 0.f, ng = 0.f, no = 0.f;
        if (active) {
            y[((size_t)t * B_SZ + bglob) * H_SZ + j] = h;
            if (t + 1 < T_STEPS) {
                size_t base = ((size_t)(t + 1) * G4H + j) * B_SZ + bglob;
                ni = gx[base];
                nf = gx[base + 200 * B_SZ];
                ng = gx[base + 400 * B_SZ];
                no = gx[base + 600 * B_SZ];
            } else {
                hn[bglob * H_SZ + j] = h;
                cn[bglob * H_SZ + j] = c;
            }
        }

        asm volatile("barrier.cluster.wait.aligned;" ::: "memory");

        gi = ni; gf = nf; gg = ng; go = no;
    }
}

// ---------------- launch ----------------------------------------------------
extern "C" void kernel_launch(void* const* d_in, const int* in_sizes, int n_in,
                              void* d_out, int out_size)
{
    const float* x     = (const float*)d_in[0];
    const float* w_ih0 = (const float*)d_in[1];
    const float* w_hh0 = (const float*)d_in[2];
    const float* b_ih0 = (const float*)d_in[3];
    const float* b_hh0 = (const float*)d_in[4];
    const float* w_ih1 = (const float*)d_in[5];
    const float* w_hh1 = (const float*)d_in[6];
    const float* b_ih1 = (const float*)d_in[7];
    const float* b_hh1 = (const float*)d_in[8];
    const float* w_fc  = (const float*)d_in[9];
    const float* b_fc  = (const float*)d_in[10];

    float* out = (float*)d_out;
    float* hn  = out + (size_t)T_STEPS * B_SZ * OUT_SZ;   // [2][B][H]
    float* cn  = hn + 2 * B_SZ * H_SZ;

    void *gx_p, *y_p;
    cudaGetSymbolAddress(&gx_p, g_gx);
    cudaGetSymbolAddress(&y_p,  g_y);
    float* gxb = (float*)gx_p;
    float* yb  = (float*)y_p;

    const int lstm_smem = (W_WORDS + 2 * HS_BUF) * 4;     // ~166.5 KB
    cudaFuncSetAttribute(lstm_kernel,
                         cudaFuncAttributeMaxDynamicSharedMemorySize, lstm_smem);

    dim3 lstm_grid(CL_N, B_SZ / BG_SZ);                   // (4, 32)

    // ----- layer 0 -----
    proj_kernel<<<dim3(50, T_STEPS), 128>>>(x, w_ih0, b_ih0, b_hh0,
                                            gxb, IN_SZ, G4H, 0);
    lstm_kernel<<<lstm_grid, NTHR, lstm_smem>>>(gxb, w_hh0, yb, hn, cn);

    // ----- layer 1 -----
    proj_kernel<<<dim3(50, T_STEPS), 128>>>(yb, w_ih1, b_ih1, b_hh1,
                                            gxb, H_SZ, G4H, 0);
    lstm_kernel<<<lstm_grid, NTHR, lstm_smem>>>(gxb, w_hh1, yb,
                                                hn + B_SZ * H_SZ,
                                                cn + B_SZ * H_SZ);

    // ----- FC head -----
    proj_kernel<<<dim3(6, T_STEPS), 128>>>(yb, w_fc, b_fc, nullptr,
                                           out, H_SZ, OUT_SZ, 1);
}

// round 11
// speedup vs baseline: 1.1931x; 1.1931x over previous
#include <cuda_runtime.h>
#include <cstdint>
#include <cstddef>

#define T_STEPS 2048
#define B_SZ    128
#define H_SZ    200
#define IN_SZ   88
#define OUT_SZ  88
#define G4H     800
#define CL_N    4        // CTAs per cluster
#define BG_SZ   4        // batches per cluster (batch-group)
#define U_PER   50       // hidden units per CTA

// ---------------- scratch (static device globals) ---------------------------
__device__ float g_gx[(size_t)T_STEPS * G4H * B_SZ];   // [T][4H][B]
__device__ float g_y [(size_t)T_STEPS * B_SZ * H_SZ];  // [T][B][H]

__device__ __forceinline__ float sigm(float x) {
    return __frcp_rn(1.0f + __expf(-x));
}
__device__ __forceinline__ float tanh_f(float x) {
    float e = __expf(-2.0f * fabsf(x));
    float r = (1.0f - e) * __frcp_rn(1.0f + e);
    return copysignf(r, x);
}
__device__ __forceinline__ float2 unpack2(unsigned long long v) {
    float2 r;
    asm("mov.b64 {%0, %1}, %2;" : "=f"(r.x), "=f"(r.y) : "l"(v));
    return r;
}
#define FMA2(acc, a, b) \
    asm("fma.rn.f32x2 %0, %1, %2, %0;" : "+l"(acc) : "l"(a), "l"(b))

// ---------------- projection GEMM (unchanged — known good) -------------------
__global__ void proj_kernel(const float* __restrict__ A, const float* __restrict__ W,
                            const float* __restrict__ b1, const float* __restrict__ b2,
                            float* __restrict__ out, int K, int R, int mode)
{
    __shared__ float w_sm[16 * H_SZ];   // max K = 200

    int t   = blockIdx.y;
    int r0  = blockIdx.x * 16;
    int tid = threadIdx.x;
    int K4  = K >> 2;

    for (int i = tid; i < 16 * K4; i += 128) {
        int r = i / K4, kk = i % K4, rg = r0 + r;
        float4 v = make_float4(0.f, 0.f, 0.f, 0.f);
        if (rg < R) v = ((const float4*)(W + (size_t)rg * K))[kk];
        ((float4*)w_sm)[i] = v;
    }
    __syncthreads();

    int b = tid;
    unsigned long long acc[16];
#pragma unroll
    for (int r = 0; r < 16; r++) acc[r] = 0ULL;

    const ulonglong2* xrow = (const ulonglong2*)(A + ((size_t)t * B_SZ + b) * K);
#pragma unroll 2
    for (int kk = 0; kk < K4; kk++) {
        ulonglong2 xv = __ldg(xrow + kk);
#pragma unroll
        for (int r = 0; r < 16; r++) {
            ulonglong2 wv = *((const ulonglong2*)(w_sm + r * K) + kk);
            FMA2(acc[r], xv.x, wv.x);
            FMA2(acc[r], xv.y, wv.y);
        }
    }

    if (mode == 0) {
#pragma unroll
        for (int r = 0; r < 16; r++) {
            int rg = r0 + r;
            if (rg < R) {
                float2 p = unpack2(acc[r]);
                out[((size_t)t * R + rg) * B_SZ + b] =
                    p.x + p.y + b1[rg] + b2[rg];
            }
        }
    } else {
#pragma unroll
        for (int r = 0; r < 16; r++) {
            int rg = r0 + r;
            if (rg < R) {
                float2 p = unpack2(acc[r]);
                out[((size_t)t * B_SZ + b) * R + rg] = sigm(p.x + p.y + b1[rg]);
            }
        }
    }
}

// ---------------- persistent LSTM: 4-CTA cluster + mbarrier handshake -------
// Grid (4, 32), cluster (4,1,1). Thread (tid<200): b=tid&3, u=tid>>2 —
// identical compute to the 17.9ms R8 kernel. Per-step sync replaced:
// each CTA owns 1 mbarrier (expected = 8 warps x 4 CTAs = 32); warps push
// DSMEM h-stores, __syncwarp, lane0 does 4 remote arrive.release; consumers
// try_wait.parity.acquire at the top of the next step.
#define W_WORDS  (4 * U_PER * H_SZ)             // 40000
#define HS_OFF   W_WORDS
#define HS_BUF   (BG_SZ * 204)                  // 816
#define MB_OFF   (HS_OFF + 2 * HS_BUF)          // word idx 41632 (8B aligned)
#define NTHR     256
#define N_ARRIVE (CL_N * (NTHR / 32))           // 32 arrivals per phase

__device__ __forceinline__ void mbar_wait(unsigned addr, unsigned parity) {
    asm volatile(
        "{\n\t.reg .pred P;\n"
        "W%=:\n\t"
        "mbarrier.try_wait.parity.acquire.cluster.shared::cta.b64 P, [%0], %1, 0x989680;\n\t"
        "@!P bra W%=;\n\t}"
        :: "r"(addr), "r"(parity) : "memory");
}

__global__ void __cluster_dims__(CL_N, 1, 1)
lstm_kernel(const float* __restrict__ gx,   // [T][4H][B]
            const float* __restrict__ whh,  // [4H][H]
            float* __restrict__ y,          // [T][B][H]
            float* __restrict__ hn, float* __restrict__ cn)
{
    extern __shared__ float sm[];
    float* w_sm = sm;                       // 40000 floats

    int tid = threadIdx.x;
    int jg  = blockIdx.x;                   // cluster rank
    int bg  = blockIdx.y;                   // batch-group 0..31

    // stage this CTA's weight slice (coalesced over k)
    for (int i = tid; i < W_WORDS; i += NTHR) {
        int g = i / (U_PER * H_SZ), rem = i % (U_PER * H_SZ);
        int u = rem / H_SZ, k = rem % H_SZ;
        w_sm[i] = whh[(size_t)(g * H_SZ + jg * U_PER + u) * H_SZ + k];
    }
    // zero h double-buffer
    for (int i = tid; i < 2 * HS_BUF; i += NTHR) sm[HS_OFF + i] = 0.f;

    unsigned smem_u32;
    {
        unsigned long long tmp;
        asm("cvta.to.shared.u64 %0, %1;" : "=l"(tmp) : "l"(sm));
        smem_u32 = (unsigned)tmp;
    }
    unsigned mbar_addr = smem_u32 + MB_OFF * 4u;

    if (tid == 0) {
        asm volatile("mbarrier.init.shared.b64 [%0], %1;"
                     :: "r"(mbar_addr), "r"(N_ARRIVE) : "memory");
    }
    __syncthreads();
    // all CTAs initialized (smem + mbar) before any remote op can land
    asm volatile("barrier.cluster.arrive.aligned;" ::: "memory");
    asm volatile("barrier.cluster.wait.aligned;"   ::: "memory");

    bool active = tid < 200;
    int b = tid & 3, u = tid >> 2;
    int j = jg * U_PER + u, bglob = bg * BG_SZ + b;
    float c = 0.f;

    // remote addresses: h slot (per rank) + mbarrier (per rank)
    unsigned rh[CL_N], rm[CL_N];
    {
        unsigned hloc = smem_u32 + (HS_OFF + b * 204 + j) * 4u;
#pragma unroll
        for (int r = 0; r < CL_N; r++) {
            asm("mapa.shared::cluster.u32 %0, %1, %2;"
                : "=r"(rh[r]) : "r"(hloc), "r"(r));
            asm("mapa.shared::cluster.u32 %0, %1, %2;"
                : "=r"(rm[r]) : "r"(mbar_addr), "r"(r));
        }
    }

    const ulonglong2* wi2 = (const ulonglong2*)(w_sm + 0 * U_PER * H_SZ + u * H_SZ);
    const ulonglong2* wf2 = (const ulonglong2*)(w_sm + 1 * U_PER * H_SZ + u * H_SZ);
    const ulonglong2* wg2 = (const ulonglong2*)(w_sm + 2 * U_PER * H_SZ + u * H_SZ);
    const ulonglong2* wo2 = (const ulonglong2*)(w_sm + 3 * U_PER * H_SZ + u * H_SZ);

    // preload gx for t = 0
    float gi = 0.f, gf = 0.f, gg = 0.f, go = 0.f;
    if (active) {
        size_t base = (size_t)j * B_SZ + bglob;
        gi = gx[base];
        gf = gx[base + 200 * B_SZ];
        gg = gx[base + 400 * B_SZ];
        go = gx[base + 600 * B_SZ];
    }

    for (int t = 0; t < T_STEPS; t++) {
        // wait for step-t h data (phase t-1 completion), acquire DSMEM stores
        if (t > 0) mbar_wait(mbar_addr, (unsigned)((t - 1) & 1));

        float h = 0.f;
        if (active) {
            const ulonglong2* h2 =
                (const ulonglong2*)(sm + HS_OFF + (t & 1) * HS_BUF + b * 204);
            unsigned long long ai = 0ULL, af = 0ULL, ag = 0ULL, ao = 0ULL;
#pragma unroll
            for (int kk = 0; kk < 50; kk++) {
                ulonglong2 hv = h2[kk];
                ulonglong2 w;
                w = wi2[kk]; FMA2(ai, hv.x, w.x); FMA2(ai, hv.y, w.y);
                w = wf2[kk]; FMA2(af, hv.x, w.x); FMA2(af, hv.y, w.y);
                w = wg2[kk]; FMA2(ag, hv.x, w.x); FMA2(ag, hv.y, w.y);
                w = wo2[kk]; FMA2(ao, hv.x, w.x); FMA2(ao, hv.y, w.y);
            }
            float2 pi = unpack2(ai), pf = unpack2(af);
            float2 pg = unpack2(ag), po = unpack2(ao);
            float I = sigm(pi.x + pi.y + gi);
            float F = sigm(pf.x + pf.y + gf);
            float G = tanh_f(pg.x + pg.y + gg);
            float O = sigm(po.x + po.y + go);
            c = F * c + I * G;
            h = O * tanh_f(c);

            // push h into every cluster CTA's next-step buffer
            if (t + 1 < T_STEPS) {
                unsigned bofs = (unsigned)(((t + 1) & 1) * (HS_BUF * 4));
#pragma unroll
                for (int r = 0; r < CL_N; r++) {
                    asm volatile("st.shared::cluster.f32 [%0], %1;"
                                 :: "r"(rh[r] + bofs), "f"(h) : "memory");
                }
            }
        }

        // per-warp arrive: syncwarp orders lanes' stores before lane0's
        // release-arrives (fire-and-forget; flight off the critical path)
        if (t + 1 < T_STEPS) {
            __syncwarp();
            if ((tid & 31) == 0) {
#pragma unroll
                for (int r = 0; r < CL_N; r++) {
                    asm volatile(
                        "mbarrier.arrive.release.cluster.shared::cluster.b64 _, [%0];"
                        :: "r"(rm[r]) : "memory");
                }
            }
        }

        // outputs + next-step gx prefetch overlap peer skew (before next wait)
        float ni = 0.f, nf = 0.f, ng = 0.f, no = 0.f;
        if (active) {
            y[((size_t)t * B_SZ + bglob) * H_SZ + j] = h;
            if (t + 1 < T_STEPS) {
                size_t base = ((size_t)(t + 1) * G4H + j) * B_SZ + bglob;
                ni = gx[base];
                nf = gx[base + 200 * B_SZ];
                ng = gx[base + 400 * B_SZ];
                no = gx[base + 600 * B_SZ];
            } else {
                hn[bglob * H_SZ + j] = h;
                cn[bglob * H_SZ + j] = c;
            }
        }

        gi = ni; gf = nf; gg = ng; go = no;
    }

    // keep smem/mbar alive until all cluster traffic drained
    asm volatile("barrier.cluster.arrive.aligned;" ::: "memory");
    asm volatile("barrier.cluster.wait.aligned;"   ::: "memory");
}

// ---------------- launch ----------------------------------------------------
extern "C" void kernel_launch(void* const* d_in, const int* in_sizes, int n_in,
                              void* d_out, int out_size)
{
    const float* x     = (const float*)d_in[0];
    const float* w_ih0 = (const float*)d_in[1];
    const float* w_hh0 = (const float*)d_in[2];
    const float* b_ih0 = (const float*)d_in[3];
    const float* b_hh0 = (const float*)d_in[4];
    const float* w_ih1 = (const float*)d_in[5];
    const float* w_hh1 = (const float*)d_in[6];
    const float* b_ih1 = (const float*)d_in[7];
    const float* b_hh1 = (const float*)d_in[8];
    const float* w_fc  = (const float*)d_in[9];
    const float* b_fc  = (const float*)d_in[10];

    float* out = (float*)d_out;
    float* hn  = out + (size_t)T_STEPS * B_SZ * OUT_SZ;   // [2][B][H]
    float* cn  = hn + 2 * B_SZ * H_SZ;

    void *gx_p, *y_p;
    cudaGetSymbolAddress(&gx_p, g_gx);
    cudaGetSymbolAddress(&y_p,  g_y);
    float* gxb = (float*)gx_p;
    float* yb  = (float*)y_p;

    const int lstm_smem = (MB_OFF + 4) * 4;               // ~166.6 KB
    cudaFuncSetAttribute(lstm_kernel,
                         cudaFuncAttributeMaxDynamicSharedMemorySize, lstm_smem);

    dim3 lstm_grid(CL_N, B_SZ / BG_SZ);                   // (4, 32)

    // ----- layer 0 -----
    proj_kernel<<<dim3(50, T_STEPS), 128>>>(x, w_ih0, b_ih0, b_hh0,
                                            gxb, IN_SZ, G4H, 0);
    lstm_kernel<<<lstm_grid, NTHR, lstm_smem>>>(gxb, w_hh0, yb, hn, cn);

    // ----- layer 1 -----
    proj_kernel<<<dim3(50, T_STEPS), 128>>>(yb, w_ih1, b_ih1, b_hh1,
                                            gxb, H_SZ, G4H, 0);
    lstm_kernel<<<lstm_grid, NTHR, lstm_smem>>>(gxb, w_hh1, yb,
                                                hn + B_SZ * H_SZ,
                                                cn + B_SZ * H_SZ);

    // ----- FC head -----
    proj_kernel<<<dim3(6, T_STEPS), 128>>>(yb, w_fc, b_fc, nullptr,
                                           out, H_SZ, OUT_SZ, 1);
}